// round 9
// baseline (speedup 1.0000x reference)
#include <cuda_runtime.h>
#include <cuda_bf16.h>
#include <cstdint>

#define NJ     32
#define TPB    128
#define BPB    128                    // one batch per thread
#define NS     3                      // cp.async ring depth (group-granular)
#define INROW  36                     // words/record/group: 9 float4, stride 36
                                      //  -> 16B-aligned AND conflict-free LDS.128
#define STAGEW (BPB * INROW)          // 4608 words = 18,432 B per stage
#define OUTROW 100                    // 96 pos words + 4 pad -> conflict-free STS.128
#define SMEM_WORDS (NS * STAGEW + BPB * OUTROW)   // 26,624 words
#define SMEM_BYTES (SMEM_WORDS * 4)               // 106,496 B -> 2 CTAs/SM
#define GRID   296                    // 148 SMs x 2 resident CTAs, persistent

__device__ __forceinline__ void cp_async16(uint32_t s_addr, const void* g_ptr) {
    asm volatile("cp.async.cg.shared.global [%0], [%1], 16;\n"
                 :: "r"(s_addr), "l"(g_ptr));
}
__device__ __forceinline__ void cp_commit() {
    asm volatile("cp.async.commit_group;\n" ::: "memory");
}
__device__ __forceinline__ void cp_wait2() { asm volatile("cp.async.wait_group 2;" ::: "memory"); }
__device__ __forceinline__ void cp_wait1() { asm volatile("cp.async.wait_group 1;" ::: "memory"); }
__device__ __forceinline__ void cp_wait0() { asm volatile("cp.async.wait_group 0;" ::: "memory"); }

__global__ void __launch_bounds__(TPB)
fk32_kernel(const float* __restrict__ angles,
            const float* __restrict__ offs,
            float* __restrict__ out,
            int batch)
{
    extern __shared__ float s[];
    const int t   = threadIdx.x;
    const int bid = blockIdx.x;
    const uint32_t sbase = (uint32_t)__cvta_generic_to_shared(s);

    const int ntiles = (batch + BPB - 1) / BPB;      // 2048
    if (bid >= ntiles) return;

    const int par[NJ] = {-1,0,1,2,3,4,0,6,7,8,9,0,11,12,13,14,12,16,17,18,
                         19,20,19,22,12,24,25,26,27,28,27,30};
    const bool isp[NJ] = {1,1,1,1,1,0,1,1,1,1,0,1,1,1,1,0,
                          1,1,1,1,1,0,1,0,1,1,1,1,1,0,1,0};

    const int nmine = (ntiles - bid + GRID - 1) / GRID;
    const int M     = nmine * 8;                     // my chunk count (tile,group)

    const float4* __restrict__ angv = reinterpret_cast<const float4*>(angles);
    float4* outv_s = reinterpret_cast<float4*>(s + NS * STAGEW);

    // ---- chunk issuer: chunk mm = (local tile mm>>3, group mm&7) -> stage mm%3
    auto issue = [&](int mm) {
        const int tile2 = bid + (mm >> 3) * GRID;
        const int g2    = mm & 7;
        const int st    = mm % NS;
        const size_t gbase = (size_t)tile2 * BPB * 72 + (size_t)g2 * 9;
        const uint32_t sb  = sbase + (uint32_t)(st * STAGEW) * 4u;
        #pragma unroll
        for (int i = 0; i < 9; ++i) {
            int e  = t + i * TPB;         // 0..1151
            int c  = e / 9;               // record in tile
            int ip = e - c * 9;           // float4 within 144B slice
            int cc = c;
            if ((size_t)tile2 * BPB + (size_t)cc >= (size_t)batch) cc = 0;
            cp_async16(sb + (uint32_t)(cc * INROW + ip * 4) * 4u,
                       angv + (gbase + (size_t)cc * 72 + ip));
        }
        cp_commit();
    };

    // ---- prologue: fill the ring
    #pragma unroll
    for (int mm = 0; mm < NS; ++mm)
        if (mm < M) issue(mm);

    float R[NJ][9];
    float P[NJ][3];

    int m = 0;                                        // current chunk
    for (int tile = bid; tile < ntiles; tile += GRID) {
        #pragma unroll
        for (int g = 0; g < 8; ++g) {
            // ---- wait: chunk m landed (ring keeps <= NS-1 younger pending)
            if (m + 3 <= M)      cp_wait2();
            else if (m + 2 == M) cp_wait1();
            else                 cp_wait0();
            __syncthreads();      // publish stage; also fences prior flush/STS

            // ---- consume: 9 conflict-free LDS.128 from stage m%3
            const float4* stv =
                reinterpret_cast<const float4*>(s + (m % NS) * STAGEW) + t * 9;
            float a[36];
            #pragma unroll
            for (int q = 0; q < 9; ++q) {
                float4 v = stv[q];
                a[4*q+0] = v.x; a[4*q+1] = v.y; a[4*q+2] = v.z; a[4*q+3] = v.w;
            }

            // ---- FK for joints 4g..4g+3 (all indices compile-time)
            #pragma unroll
            for (int jj = 0; jj < 4; ++jj) {
                const int j = g * 4 + jj;
                const float* Aj = &a[jj * 9];
                if (j == 0) {
                    #pragma unroll
                    for (int q = 0; q < 9; ++q) R[0][q] = Aj[q];
                    P[0][0] = 0.f; P[0][1] = 0.f; P[0][2] = 0.f;
                } else {
                    const int p = par[j];
                    const float o0 = __ldg(&offs[j*3+0]);
                    const float o1 = __ldg(&offs[j*3+1]);
                    const float o2 = __ldg(&offs[j*3+2]);
                    #pragma unroll
                    for (int l = 0; l < 3; ++l) {
                        P[j][l] = fmaf(o0, R[p][0*3+l],
                                  fmaf(o1, R[p][1*3+l],
                                  fmaf(o2, R[p][2*3+l], P[p][l])));
                    }
                    if (isp[j]) {
                        #pragma unroll
                        for (int i = 0; i < 3; ++i) {
                            #pragma unroll
                            for (int l = 0; l < 3; ++l) {
                                R[j][i*3+l] = fmaf(Aj[i*3+0], R[p][0*3+l],
                                              fmaf(Aj[i*3+1], R[p][1*3+l],
                                                   Aj[i*3+2] * R[p][2*3+l]));
                            }
                        }
                    }
                }
            }

            // ---- stage positions: 3 conflict-free STS.128 (row = 25 f4 slots)
            {
                const int j0 = g * 4;
                float4* orow = outv_s + t * (OUTROW / 4);
                orow[g*3+0] = make_float4(P[j0+0][0], P[j0+0][1], P[j0+0][2], P[j0+1][0]);
                orow[g*3+1] = make_float4(P[j0+1][1], P[j0+1][2], P[j0+2][0], P[j0+2][1]);
                orow[g*3+2] = make_float4(P[j0+2][2], P[j0+3][0], P[j0+3][1], P[j0+3][2]);
            }

            __syncthreads();      // stage m fully consumed by all threads

            // ---- refill the ring immediately (keeps DRAM streaming)
            if (m + NS < M) issue(m + NS);
            ++m;

            // ---- tile complete: coalesced float4 flush (overlaps next loads)
            if (g == 7) {
                float4* dstv = reinterpret_cast<float4*>(out) + (size_t)tile * BPB * 24;
                #pragma unroll
                for (int k = 0; k < 24; ++k) {
                    int q   = t + k * TPB;        // 0..3071
                    int c   = q / 24;
                    int off = q - c * 24;
                    if ((size_t)tile * BPB + (size_t)c < (size_t)batch)
                        dstv[q] = outv_s[c * (OUTROW / 4) + off];
                }
                // no barrier needed: next chunk's post-wait __syncthreads()
                // fences this flush before any new STS touches the out tile.
            }
        }
    }
}

extern "C" void kernel_launch(void* const* d_in, const int* in_sizes, int n_in,
                              void* d_out, int out_size)
{
    const float* angles = (const float*)d_in[0];
    const float* offs   = (const float*)d_in[1];
    float* out          = (float*)d_out;

    int batch = in_sizes[0] / (NJ * 9);              // 262144

    static bool attr_done = false;
    if (!attr_done) {
        cudaFuncSetAttribute(fk32_kernel,
                             cudaFuncAttributeMaxDynamicSharedMemorySize,
                             SMEM_BYTES);
        attr_done = true;
    }

    fk32_kernel<<<GRID, TPB, SMEM_BYTES>>>(angles, offs, out, batch);
}

// round 10
// speedup vs baseline: 1.1945x; 1.1945x over previous
#include <cuda_runtime.h>
#include <cuda_bf16.h>
#include <cstdint>

#define NJ    32
#define TPB   32                      // single warp per CTA -> warp-sync only
#define BPB   32                      // one batch per thread
#define RECW  292                     // 288 + 4 pad words: 16B-aligned, lane
                                      // stride 292 -> conflict-free LDS.128
#define SMEM_BYTES (BPB * RECW * 4)   // 37,376 B -> 6 CTAs/SM (224.3/228 KB)
#define GRID  888                     // 148 SMs x 6 resident CTAs, persistent

__device__ __forceinline__ void cp_async16(uint32_t s_addr, const void* g_ptr) {
    asm volatile("cp.async.cg.shared.global [%0], [%1], 16;\n"
                 :: "r"(s_addr), "l"(g_ptr));
}

__global__ void __launch_bounds__(TPB)
fk32_kernel(const float* __restrict__ angles,
            const float* __restrict__ offs,
            float* __restrict__ out,
            int batch)
{
    extern __shared__ float s[];          // BPB records of RECW floats
    const int t = threadIdx.x;
    const uint32_t sbase = (uint32_t)__cvta_generic_to_shared(s);

    const int par[NJ] = {-1,0,1,2,3,4,0,6,7,8,9,0,11,12,13,14,12,16,17,18,
                         19,20,19,22,12,24,25,26,27,28,27,30};
    const bool isp[NJ] = {1,1,1,1,1,0,1,1,1,1,0,1,1,1,1,0,
                          1,1,1,1,1,0,1,0,1,1,1,1,1,0,1,0};

    const int ntiles = (batch + BPB - 1) / BPB;       // 8192

    for (int tile = blockIdx.x; tile < ntiles; tile += GRID) {
        const size_t B0 = (size_t)tile * BPB;

        // ===== phase 1: one dense cp.async sweep (gmem fully contiguous) ====
        // tile = 32 records x 72 float4 = 2304 float4, 72 per thread.
        {
            const float4* srcv = reinterpret_cast<const float4*>(angles) + B0 * 72;
            #pragma unroll
            for (int k = 0; k < 72; ++k) {
                int q   = t + k * TPB;        // 0..2303
                int c   = q / 72;             // record in tile
                int off = q - c * 72;         // float4 within record
                cp_async16(sbase + (uint32_t)(c * RECW + off * 4) * 4u,
                           srcv + q);
            }
            asm volatile("cp.async.commit_group;\n" ::: "memory");
            asm volatile("cp.async.wait_group 0;\n" ::: "memory");
            __syncwarp();     // warp-scope publish: all lanes' copies landed
        }

        // ===== phase 2: per-thread full FK from own smem record ============
        {
            float4* recv = reinterpret_cast<float4*>(s + t * RECW);
            float R[NJ][9];
            float P[NJ][3];

            #pragma unroll
            for (int g = 0; g < 8; ++g) {
                // 9 conflict-free LDS.128: this group's 4 rotation matrices
                float a[36];
                #pragma unroll
                for (int q = 0; q < 9; ++q) {
                    float4 v = recv[g * 9 + q];
                    a[4*q+0] = v.x; a[4*q+1] = v.y; a[4*q+2] = v.z; a[4*q+3] = v.w;
                }

                #pragma unroll
                for (int jj = 0; jj < 4; ++jj) {
                    const int j = g * 4 + jj;
                    const float* Aj = &a[jj * 9];
                    if (j == 0) {
                        #pragma unroll
                        for (int q = 0; q < 9; ++q) R[0][q] = Aj[q];
                        P[0][0] = 0.f; P[0][1] = 0.f; P[0][2] = 0.f;
                    } else {
                        const int p = par[j];
                        const float o0 = __ldg(&offs[j*3+0]);
                        const float o1 = __ldg(&offs[j*3+1]);
                        const float o2 = __ldg(&offs[j*3+2]);
                        #pragma unroll
                        for (int l = 0; l < 3; ++l) {
                            P[j][l] = fmaf(o0, R[p][0*3+l],
                                      fmaf(o1, R[p][1*3+l],
                                      fmaf(o2, R[p][2*3+l], P[p][l])));
                        }
                        if (isp[j]) {
                            #pragma unroll
                            for (int i = 0; i < 3; ++i) {
                                #pragma unroll
                                for (int l = 0; l < 3; ++l) {
                                    R[j][i*3+l] = fmaf(Aj[i*3+0], R[p][0*3+l],
                                                  fmaf(Aj[i*3+1], R[p][1*3+l],
                                                       Aj[i*3+2] * R[p][2*3+l]));
                                }
                            }
                        }
                    }
                }

                // pack positions in place: words [12g,12g+12) belong to input
                // group floor(g/3) <= g, already consumed (group g is in regs).
                const int j0 = g * 4;
                recv[g*3+0] = make_float4(P[j0+0][0], P[j0+0][1], P[j0+0][2], P[j0+1][0]);
                recv[g*3+1] = make_float4(P[j0+1][1], P[j0+1][2], P[j0+2][0], P[j0+2][1]);
                recv[g*3+2] = make_float4(P[j0+2][2], P[j0+3][0], P[j0+3][1], P[j0+3][2]);
            }
        }
        __syncwarp();         // packed positions visible warp-wide

        // ===== phase 3: coalesced float4 flush (dense 128B lines) ==========
        {
            float4* dstv = reinterpret_cast<float4*>(out) + B0 * 24;
            const float4* sv = reinterpret_cast<const float4*>(s);
            #pragma unroll
            for (int k = 0; k < 24; ++k) {
                int q   = t + k * TPB;        // 0..767
                int c   = q / 24;
                int off = q - c * 24;
                if (B0 + (size_t)c < (size_t)batch)
                    dstv[q] = sv[c * (RECW / 4) + off];
            }
        }
        __syncwarp();         // flush reads done before next tile's cp.async
    }
}

extern "C" void kernel_launch(void* const* d_in, const int* in_sizes, int n_in,
                              void* d_out, int out_size)
{
    const float* angles = (const float*)d_in[0];
    const float* offs   = (const float*)d_in[1];
    float* out          = (float*)d_out;

    int batch = in_sizes[0] / (NJ * 9);               // 262144

    static bool attr_done = false;
    if (!attr_done) {
        cudaFuncSetAttribute(fk32_kernel,
                             cudaFuncAttributeMaxDynamicSharedMemorySize,
                             SMEM_BYTES);
        attr_done = true;
    }

    fk32_kernel<<<GRID, TPB, SMEM_BYTES>>>(angles, offs, out, batch);
}